// round 12
// baseline (speedup 1.0000x reference)
#include <cuda_runtime.h>
#include <math.h>

// Problem constants (fixed by setup_inputs)
#define NN   100000
#define EE   3200000
#define DIN  512
#define DH   32
#define DC   40
#define PEPS 1e-5f

// ---------------- scratch (device globals; no allocation allowed) ----------
__device__ int   g_deg[NN];
__device__ float g_dinv[NN];
__device__ int   g_rowptr[NN + 1];
__device__ int   g_wcnt[NN];
__device__ int2  g_edges[EE + NN];               // {src, __float_as_int(norm)} sorted by dst
__device__ float g_bufA[(size_t)NN * DH];
__device__ float g_bufB[(size_t)NN * DH];
__device__ float g_bufC[(size_t)NN * DC];
__device__ float g_stats[DH + 1];                // colsums[32], sumsq
__device__ float g_pn[DH + 1];                   // means[32], scale

// ---------------- setup kernels --------------------------------------------
__global__ void k_zero(int n) {
    int i = blockIdx.x * blockDim.x + threadIdx.x;
    if (i < n) { g_deg[i] = 0; g_wcnt[i] = 0; }
}

// edge_index is int32 on device (JAX x64 disabled downcasts jnp.int64 -> int32)
__global__ void k_hist(const int* __restrict__ ei, int E) {
    int e = blockIdx.x * blockDim.x + threadIdx.x;
    if (e < E) atomicAdd(&g_deg[ei[E + e]], 1);
}

__global__ void k_dinv(int n) {
    int i = blockIdx.x * blockDim.x + threadIdx.x;
    if (i < n) g_dinv[i] = rsqrtf((float)(g_deg[i] + 1));   // +1 self loop
}

// single-block exclusive scan of (deg[i]+1) -> rowptr
__global__ void k_scan(int n) {
    __shared__ int sb[1024];
    int tid   = threadIdx.x;
    int chunk = (n + 1023) >> 10;
    int s0 = tid * chunk;
    int s1 = min(s0 + chunk, n);
    int s  = 0;
    for (int i = s0; i < s1; i++) s += g_deg[i] + 1;
    sb[tid] = s;
    __syncthreads();
    for (int off = 1; off < 1024; off <<= 1) {
        int v = (tid >= off) ? sb[tid - off] : 0;
        __syncthreads();
        sb[tid] += v;
        __syncthreads();
    }
    int run = (tid == 0) ? 0 : sb[tid - 1];
    for (int i = s0; i < s1; i++) { g_rowptr[i] = run; run += g_deg[i] + 1; }
    if (s0 <= n && s1 == n) g_rowptr[n] = run;
}

__global__ void k_scatter(const int* __restrict__ ei, int E, int n) {
    int e = blockIdx.x * blockDim.x + threadIdx.x;
    if (e < E) {
        int s = ei[e];
        int d = ei[E + e];
        int pos = g_rowptr[d] + atomicAdd(&g_wcnt[d], 1);
        g_edges[pos] = make_int2(s, __float_as_int(g_dinv[s] * g_dinv[d]));
    } else if (e < E + n) {
        int i   = e - E;
        float v = g_dinv[i];
        int pos = g_rowptr[i] + atomicAdd(&g_wcnt[i], 1);
        g_edges[pos] = make_int2(i, __float_as_int(v * v));
    }
}

// ---------------- GEMM0: bufA = x[n,512] @ W0[512,32] ----------------------
// block: 256 thr = 8 warps, 64 rows/block, warp -> 8 rows, lane -> col.
__global__ void __launch_bounds__(256) k_gemm0(const float* __restrict__ x,
                                               const float* __restrict__ W0, int n) {
    __shared__ float As[64 * 32];      // A tile, row-major
    __shared__ float WsT[32 * 36];     // W tile transposed [col][kk], padded
    int tid  = threadIdx.x;
    int lane = tid & 31;
    int warp = tid >> 5;
    int rb   = blockIdx.x * 64;

    float acc[8];
#pragma unroll
    for (int i = 0; i < 8; i++) acc[i] = 0.f;

    for (int kt = 0; kt < DIN; kt += 32) {
        // W tile: coalesced float4 read, transposed scalar smem store
        {
            float4 wv = *(const float4*)&W0[kt * 32 + tid * 4];
            int kk = tid >> 3;
            int cb = (tid & 7) * 4;
            WsT[(cb + 0) * 36 + kk] = wv.x;
            WsT[(cb + 1) * 36 + kk] = wv.y;
            WsT[(cb + 2) * 36 + kk] = wv.z;
            WsT[(cb + 3) * 36 + kk] = wv.w;
        }
        // A tile: 64 rows x 32 k, 2x float4 per thread
        {
            int row = tid >> 2;
            int seg = (tid & 3) * 8;
            int gr  = rb + row;
            float4 v0, v1;
            if (gr < n) {
                const float4* p = (const float4*)(x + (size_t)gr * DIN + kt + seg);
                v0 = p[0]; v1 = p[1];
            } else {
                v0 = make_float4(0.f, 0.f, 0.f, 0.f); v1 = v0;
            }
            *(float4*)&As[row * 32 + seg]     = v0;
            *(float4*)&As[row * 32 + seg + 4] = v1;
        }
        __syncthreads();
#pragma unroll
        for (int kk4 = 0; kk4 < 8; kk4++) {
            float4 w4 = *(const float4*)&WsT[lane * 36 + kk4 * 4];
#pragma unroll
            for (int i = 0; i < 8; i++) {
                float4 a4 = *(const float4*)&As[(warp * 8 + i) * 32 + kk4 * 4];
                acc[i] += a4.x * w4.x;
                acc[i] += a4.y * w4.y;
                acc[i] += a4.z * w4.z;
                acc[i] += a4.w * w4.w;
            }
        }
        __syncthreads();
    }
#pragma unroll
    for (int i = 0; i < 8; i++) {
        int gr = rb + warp * 8 + i;
        if (gr < n) g_bufA[(size_t)gr * DH + lane] = acc[i];
    }
}

// ---------------- aggregation (CSR, warp-per-node, lane-per-feature) -------
__global__ void __launch_bounds__(256) k_agg32(int sel, int n) {
    const float* __restrict__ hin  = sel ? g_bufB : g_bufA;
    float*       __restrict__ hout = sel ? g_bufA : g_bufB;
    int node = blockIdx.x * 8 + (threadIdx.x >> 5);
    if (node >= n) return;
    int lane = threadIdx.x & 31;
    int p  = g_rowptr[node];
    int pe = g_rowptr[node + 1];
    float acc = 0.f;
    for (; p + 1 < pe; p += 2) {
        int2 e0 = g_edges[p];
        int2 e1 = g_edges[p + 1];
        float h0 = hin[(size_t)e0.x * DH + lane];
        float h1 = hin[(size_t)e1.x * DH + lane];
        acc += h0 * __int_as_float(e0.y);
        acc += h1 * __int_as_float(e1.y);
    }
    if (p < pe) {
        int2 e0 = g_edges[p];
        acc += hin[(size_t)e0.x * DH + lane] * __int_as_float(e0.y);
    }
    hout[(size_t)node * DH + lane] = acc;
}

__global__ void __launch_bounds__(256) k_agg40(float* __restrict__ out,
                                               const float* __restrict__ bf, int n) {
    int node = blockIdx.x * 8 + (threadIdx.x >> 5);
    if (node >= n) return;
    int lane = threadIdx.x & 31;
    int p  = g_rowptr[node];
    int pe = g_rowptr[node + 1];
    float a0 = 0.f, a1 = 0.f;
    for (; p < pe; p++) {
        int2 ed  = g_edges[p];
        float nm = __int_as_float(ed.y);
        const float* hr = g_bufC + (size_t)ed.x * DC;
        a0 += hr[lane] * nm;
        if (lane < 8) a1 += hr[32 + lane] * nm;
    }
    out[(size_t)node * DC + lane] = a0 + bf[lane];
    if (lane < 8) out[(size_t)node * DC + 32 + lane] = a1 + bf[32 + lane];
}

// ---------------- PairNorm --------------------------------------------------
__global__ void k_zero_stats() {
    int i = threadIdx.x;
    if (i <= DH) g_stats[i] = 0.f;
}

__global__ void __launch_bounds__(256) k_stats(int sel, int n) {
    const float* __restrict__ src = sel ? g_bufA : g_bufB;
    int lane = threadIdx.x & 31;
    int w    = threadIdx.x >> 5;
    float cs = 0.f, ss = 0.f;
    for (int r = blockIdx.x * 8 + w; r < n; r += gridDim.x * 8) {
        float v = src[(size_t)r * DH + lane];
        cs += v;
        ss += v * v;
    }
#pragma unroll
    for (int o = 16; o; o >>= 1) ss += __shfl_down_sync(0xffffffffu, ss, o);
    atomicAdd(&g_stats[lane], cs);
    if (lane == 0) atomicAdd(&g_stats[DH], ss);
}

__global__ void k_pnfin(int n) {
    int l = threadIdx.x;               // 32 threads
    float m = g_stats[l] / (float)n;
    g_pn[l] = m;
    float mm = m * m;
#pragma unroll
    for (int o = 16; o; o >>= 1) mm += __shfl_down_sync(0xffffffffu, mm, o);
    if (l == 0) {
        float var = g_stats[DH] / (float)n - mm;
        g_pn[DH] = rsqrtf(PEPS + var);
    }
}

__global__ void __launch_bounds__(256) k_pnrelu(int sel, int n) {
    const float* __restrict__ in  = sel ? g_bufA : g_bufB;
    float*       __restrict__ out = sel ? g_bufB : g_bufA;
    int i4 = blockIdx.x * blockDim.x + threadIdx.x;     // float4 index, 8 per row
    if (i4 >= n * 8) return;
    float4 v = ((const float4*)in)[i4];
    int cb   = (i4 & 7) * 4;
    float sc = g_pn[DH];
    v.x = fmaxf((v.x - g_pn[cb + 0]) * sc, 0.f);
    v.y = fmaxf((v.y - g_pn[cb + 1]) * sc, 0.f);
    v.z = fmaxf((v.z - g_pn[cb + 2]) * sc, 0.f);
    v.w = fmaxf((v.w - g_pn[cb + 3]) * sc, 0.f);
    ((float4*)out)[i4] = v;
}

// ---------------- small GEMMs (warp-per-row, shfl broadcast) ----------------
__global__ void __launch_bounds__(256) k_gemm32(const float* __restrict__ W, int n) {
    __shared__ float Ws[32 * 32];
    for (int i = threadIdx.x; i < 32 * 32; i += 256) Ws[i] = W[i];
    __syncthreads();
    int node = blockIdx.x * 8 + (threadIdx.x >> 5);
    if (node >= n) return;
    int lane = threadIdx.x & 31;
    float hv  = g_bufA[(size_t)node * DH + lane];
    float acc = 0.f;
#pragma unroll
    for (int k = 0; k < 32; k++)
        acc += __shfl_sync(0xffffffffu, hv, k) * Ws[k * 32 + lane];
    g_bufB[(size_t)node * DH + lane] = acc;
}

__global__ void __launch_bounds__(256) k_gemm40(const float* __restrict__ W, int n) {
    __shared__ float Ws[32 * DC];
    for (int i = threadIdx.x; i < 32 * DC; i += 256) Ws[i] = W[i];
    __syncthreads();
    int node = blockIdx.x * 8 + (threadIdx.x >> 5);
    if (node >= n) return;
    int lane = threadIdx.x & 31;
    float hv = g_bufB[(size_t)node * DH + lane];
    float a0 = 0.f, a1 = 0.f;
#pragma unroll
    for (int k = 0; k < 32; k++) {
        float xv = __shfl_sync(0xffffffffu, hv, k);
        a0 += xv * Ws[k * DC + lane];
        if (lane < 8) a1 += xv * Ws[k * DC + 32 + lane];
    }
    g_bufC[(size_t)node * DC + lane] = a0;
    if (lane < 8) g_bufC[(size_t)node * DC + 32 + lane] = a1;
}

// ---------------- launch ----------------------------------------------------
extern "C" void kernel_launch(void* const* d_in, const int* in_sizes, int n_in,
                              void* d_out, int out_size) {
    const float* x  = (const float*)d_in[0];
    const int*   ei = (const int*)d_in[1];   // int32 (JAX x64 disabled)
    const float* W0 = (const float*)d_in[2];
    // d_in[3] = b0, d_in[5] = b1 : exactly cancelled by PairNorm mean subtraction
    const float* W1 = (const float*)d_in[4];
    const float* Wf = (const float*)d_in[6];
    const float* bf = (const float*)d_in[7];
    float*       out = (float*)d_out;

    const int E = in_sizes[1] / 2;
    const int n = in_sizes[0] / DIN;

    const int nb256 = (n + 255) / 256;
    const int nbW   = (n + 7) / 8;          // warp-per-node kernels

    // build normalized CSR (A + I with symmetric gcn_norm)
    k_zero   <<<nb256, 256>>>(n);
    k_hist   <<<(E + 255) / 256, 256>>>(ei, E);
    k_dinv   <<<nb256, 256>>>(n);
    k_scan   <<<1, 1024>>>(n);
    k_scatter<<<(E + n + 255) / 256, 256>>>(ei, E, n);

    // layer 0
    k_gemm0  <<<(n + 63) / 64, 256>>>(x, W0, n);           // x @ W0 -> A
    k_agg32  <<<nbW, 256>>>(0, n);                         // A -> B
    k_zero_stats<<<1, 64>>>();
    k_stats  <<<1024, 256>>>(0, n);                        // stats(B)
    k_pnfin  <<<1, 32>>>(n);
    k_pnrelu <<<(n * 8 + 255) / 256, 256>>>(0, n);         // B -> A

    // layer 1
    k_gemm32 <<<nbW, 256>>>(W1, n);                        // A @ W1 -> B
    k_agg32  <<<nbW, 256>>>(1, n);                         // B -> A
    k_zero_stats<<<1, 64>>>();
    k_stats  <<<1024, 256>>>(1, n);                        // stats(A)
    k_pnfin  <<<1, 32>>>(n);
    k_pnrelu <<<(n * 8 + 255) / 256, 256>>>(1, n);         // A -> B

    // final layer
    k_gemm40 <<<nbW, 256>>>(Wf, n);                        // B @ Wf -> C
    k_agg40  <<<nbW, 256>>>(out, bf, n);                   // C -> out (+bf)
}

// round 13
// speedup vs baseline: 1.3830x; 1.3830x over previous
#include <cuda_runtime.h>
#include <math.h>

// Problem constants (fixed by setup_inputs)
#define NN   100000
#define EE   3200000
#define DIN  512
#define DH   32
#define DC   40
#define PEPS 1e-5f
#define SCAN_B 1024
#define MAXBLK 128            // >= ceil(NN/SCAN_B)

// ---------------- scratch (device globals; no allocation allowed) ----------
__device__ int   g_deg[NN];
__device__ float g_dinv[NN];
__device__ int   g_rowptr[NN + 1];
__device__ int   g_wpos[NN];
__device__ int   g_bsum[MAXBLK];
__device__ int   g_boff[MAXBLK + 1];
__device__ int2  g_edges[EE + NN];          // {src, bits(norm)} grouped by dst
__device__ float g_bufA[(size_t)NN * DH];
__device__ float g_bufB[(size_t)NN * DH];
__device__ float g_stats0[DH + 1];
__device__ float g_stats1[DH + 1];
__device__ float g_pn[DH + 1];              // means[32], scale

// ---------------- CSR build -------------------------------------------------
__global__ void k_zero(int n) {
    int i = blockIdx.x * blockDim.x + threadIdx.x;
    if (i < n) g_deg[i] = 0;
    if (i <= DH) { g_stats0[i] = 0.f; g_stats1[i] = 0.f; }
}

__global__ void k_hist(const int* __restrict__ ei, int E) {
    int e = blockIdx.x * blockDim.x + threadIdx.x;
    if (e < E) atomicAdd(&g_deg[ei[E + e]], 1);
}

// phase 1: per-block exclusive scan of (deg+1); also dinv
__global__ void __launch_bounds__(SCAN_B) k_scan1(int n) {
    __shared__ int sb[SCAN_B];
    int i = blockIdx.x * SCAN_B + threadIdx.x;
    int v = 0;
    if (i < n) {
        int d = g_deg[i];
        v = d + 1;
        g_dinv[i] = rsqrtf((float)(d + 1));
    }
    sb[threadIdx.x] = v;
    __syncthreads();
#pragma unroll
    for (int off = 1; off < SCAN_B; off <<= 1) {
        int t = (threadIdx.x >= off) ? sb[threadIdx.x - off] : 0;
        __syncthreads();
        sb[threadIdx.x] += t;
        __syncthreads();
    }
    if (i < n) g_rowptr[i] = sb[threadIdx.x] - v;     // within-block exclusive
    if (threadIdx.x == SCAN_B - 1) g_bsum[blockIdx.x] = sb[SCAN_B - 1];
}

// phase 2: scan block sums (tiny)
__global__ void k_scan2(int nb) {
    __shared__ int sb[MAXBLK];
    int t = threadIdx.x;
    if (t < nb) sb[t] = g_bsum[t];
    __syncthreads();
    if (t == 0) {
        int run = 0;
        for (int b = 0; b < nb; b++) { int s = sb[b]; g_boff[b] = run; run += s; }
        g_boff[nb] = run;
    }
}

// phase 3: add offsets, produce rowptr + writable wpos
__global__ void __launch_bounds__(SCAN_B) k_scan3(int n, int nb) {
    int i = blockIdx.x * SCAN_B + threadIdx.x;
    if (i < n) {
        int rp = g_rowptr[i] + g_boff[blockIdx.x];
        g_rowptr[i] = rp;
        g_wpos[i]   = rp;
    }
    if (i == 0) g_rowptr[n] = g_boff[nb];
}

__global__ void k_scatter(const int* __restrict__ ei, int E, int n) {
    int e = blockIdx.x * blockDim.x + threadIdx.x;
    if (e < E) {
        int s = ei[e];
        int d = ei[E + e];
        int pos = atomicAdd(&g_wpos[d], 1);
        g_edges[pos] = make_int2(s, __float_as_int(g_dinv[s] * g_dinv[d]));
    } else if (e < E + n) {
        int i   = e - E;
        float v = g_dinv[i];
        int pos = atomicAdd(&g_wpos[i], 1);
        g_edges[pos] = make_int2(i, __float_as_int(v * v));
    }
}

// ---------------- GEMM0: bufA = x[n,512] @ W0[512,32] ----------------------
__global__ void __launch_bounds__(256) k_gemm0(const float* __restrict__ x,
                                               const float* __restrict__ W0, int n) {
    __shared__ float As[64 * 32];
    __shared__ float WsT[32 * 36];
    int tid  = threadIdx.x;
    int lane = tid & 31;
    int warp = tid >> 5;
    int rb   = blockIdx.x * 64;

    float acc[8];
#pragma unroll
    for (int i = 0; i < 8; i++) acc[i] = 0.f;

    for (int kt = 0; kt < DIN; kt += 32) {
        {
            float4 wv = *(const float4*)&W0[kt * 32 + tid * 4];
            int kk = tid >> 3;
            int cb = (tid & 7) * 4;
            WsT[(cb + 0) * 36 + kk] = wv.x;
            WsT[(cb + 1) * 36 + kk] = wv.y;
            WsT[(cb + 2) * 36 + kk] = wv.z;
            WsT[(cb + 3) * 36 + kk] = wv.w;
        }
        {
            int row = tid >> 2;
            int seg = (tid & 3) * 8;
            int gr  = rb + row;
            float4 v0, v1;
            if (gr < n) {
                const float4* p = (const float4*)(x + (size_t)gr * DIN + kt + seg);
                v0 = p[0]; v1 = p[1];
            } else {
                v0 = make_float4(0.f, 0.f, 0.f, 0.f); v1 = v0;
            }
            *(float4*)&As[row * 32 + seg]     = v0;
            *(float4*)&As[row * 32 + seg + 4] = v1;
        }
        __syncthreads();
#pragma unroll
        for (int kk4 = 0; kk4 < 8; kk4++) {
            float4 w4 = *(const float4*)&WsT[lane * 36 + kk4 * 4];
#pragma unroll
            for (int i = 0; i < 8; i++) {
                float4 a4 = *(const float4*)&As[(warp * 8 + i) * 32 + kk4 * 4];
                acc[i] += a4.x * w4.x;
                acc[i] += a4.y * w4.y;
                acc[i] += a4.z * w4.z;
                acc[i] += a4.w * w4.w;
            }
        }
        __syncthreads();
    }
#pragma unroll
    for (int i = 0; i < 8; i++) {
        int gr = rb + warp * 8 + i;
        if (gr < n) g_bufA[(size_t)gr * DH + lane] = acc[i];
    }
}

// ---------------- fused aggregation kernels --------------------------------
// warp-per-node, lane-per-feature, grid-stride. 256thr = 8 warps/block.

__device__ __forceinline__ void block_stats(float cs, float ss, float* stats,
                                            int warp, int lane) {
    __shared__ float s_cs[8][32];
    __shared__ float s_ss[8];
    s_cs[warp][lane] = cs;
#pragma unroll
    for (int o = 16; o; o >>= 1) ss += __shfl_down_sync(0xffffffffu, ss, o);
    if (lane == 0) s_ss[warp] = ss;
    __syncthreads();
    if (warp == 0) {
        float c = 0.f;
#pragma unroll
        for (int w = 0; w < 8; w++) c += s_cs[w][lane];
        atomicAdd(&stats[lane], c);
        if (lane == 0) {
            float t = 0.f;
#pragma unroll
            for (int w = 0; w < 8; w++) t += s_ss[w];
            atomicAdd(&stats[DH], t);
        }
    }
}

// layer0: B = agg(A); stats0(B)
__global__ void __launch_bounds__(256) k_aggA(int n) {
    int lane = threadIdx.x & 31;
    int warp = threadIdx.x >> 5;
    int wglob = blockIdx.x * 8 + warp;
    int wtot  = gridDim.x * 8;
    float cs = 0.f, ss = 0.f;
    for (int node = wglob; node < n; node += wtot) {
        int p  = g_rowptr[node];
        int pe = g_rowptr[node + 1];
        float acc = 0.f;
        for (; p + 1 < pe; p += 2) {
            int2 e0 = g_edges[p];
            int2 e1 = g_edges[p + 1];
            acc += g_bufA[(size_t)e0.x * DH + lane] * __int_as_float(e0.y);
            acc += g_bufA[(size_t)e1.x * DH + lane] * __int_as_float(e1.y);
        }
        if (p < pe) {
            int2 e0 = g_edges[p];
            acc += g_bufA[(size_t)e0.x * DH + lane] * __int_as_float(e0.y);
        }
        g_bufB[(size_t)node * DH + lane] = acc;
        cs += acc;
        ss += acc * acc;
    }
    block_stats(cs, ss, g_stats0, warp, lane);
}

// layer1: A = agg(pnrelu(B)) @ W1 ; stats1(A)
__global__ void __launch_bounds__(256) k_aggB(const float* __restrict__ W1, int n) {
    __shared__ float Ws[32 * 32];
    for (int i = threadIdx.x; i < 32 * 32; i += 256) Ws[i] = W1[i];
    __syncthreads();
    int lane = threadIdx.x & 31;
    int warp = threadIdx.x >> 5;
    int wglob = blockIdx.x * 8 + warp;
    int wtot  = gridDim.x * 8;
    float mu = g_pn[lane];
    float sc = g_pn[DH];
    float cs = 0.f, ss = 0.f;
    for (int node = wglob; node < n; node += wtot) {
        int p  = g_rowptr[node];
        int pe = g_rowptr[node + 1];
        float acc = 0.f;
        for (; p + 1 < pe; p += 2) {
            int2 e0 = g_edges[p];
            int2 e1 = g_edges[p + 1];
            float h0 = fmaxf((g_bufB[(size_t)e0.x * DH + lane] - mu) * sc, 0.f);
            float h1 = fmaxf((g_bufB[(size_t)e1.x * DH + lane] - mu) * sc, 0.f);
            acc += h0 * __int_as_float(e0.y);
            acc += h1 * __int_as_float(e1.y);
        }
        if (p < pe) {
            int2 e0 = g_edges[p];
            float h0 = fmaxf((g_bufB[(size_t)e0.x * DH + lane] - mu) * sc, 0.f);
            acc += h0 * __int_as_float(e0.y);
        }
        // epilogue: row = acc @ W1  (shfl broadcast)
        float o = 0.f;
#pragma unroll
        for (int k = 0; k < 32; k++)
            o += __shfl_sync(0xffffffffu, acc, k) * Ws[k * 32 + lane];
        g_bufA[(size_t)node * DH + lane] = o;
        cs += o;
        ss += o * o;
    }
    block_stats(cs, ss, g_stats1, warp, lane);
}

// layer2: out = agg(pnrelu(A)) @ Wf + bf
__global__ void __launch_bounds__(256) k_aggC(const float* __restrict__ Wf,
                                              const float* __restrict__ bf,
                                              float* __restrict__ out, int n) {
    __shared__ float Ws[32 * DC];
    __shared__ float Bs[DC];
    for (int i = threadIdx.x; i < 32 * DC; i += 256) Ws[i] = Wf[i];
    if (threadIdx.x < DC) Bs[threadIdx.x] = bf[threadIdx.x];
    __syncthreads();
    int lane = threadIdx.x & 31;
    int warp = threadIdx.x >> 5;
    int wglob = blockIdx.x * 8 + warp;
    int wtot  = gridDim.x * 8;
    float mu = g_pn[lane];
    float sc = g_pn[DH];
    for (int node = wglob; node < n; node += wtot) {
        int p  = g_rowptr[node];
        int pe = g_rowptr[node + 1];
        float acc = 0.f;
        for (; p + 1 < pe; p += 2) {
            int2 e0 = g_edges[p];
            int2 e1 = g_edges[p + 1];
            float h0 = fmaxf((g_bufA[(size_t)e0.x * DH + lane] - mu) * sc, 0.f);
            float h1 = fmaxf((g_bufA[(size_t)e1.x * DH + lane] - mu) * sc, 0.f);
            acc += h0 * __int_as_float(e0.y);
            acc += h1 * __int_as_float(e1.y);
        }
        if (p < pe) {
            int2 e0 = g_edges[p];
            float h0 = fmaxf((g_bufA[(size_t)e0.x * DH + lane] - mu) * sc, 0.f);
            acc += h0 * __int_as_float(e0.y);
        }
        // epilogue: acc @ Wf (32->40) + bf
        float a0 = 0.f, a1 = 0.f;
#pragma unroll
        for (int k = 0; k < 32; k++) {
            float xv = __shfl_sync(0xffffffffu, acc, k);
            a0 += xv * Ws[k * DC + lane];
            if (lane < 8) a1 += xv * Ws[k * DC + 32 + lane];
        }
        out[(size_t)node * DC + lane] = a0 + Bs[lane];
        if (lane < 8) out[(size_t)node * DC + 32 + lane] = a1 + Bs[32 + lane];
    }
}

// ---------------- PairNorm finalize -----------------------------------------
__global__ void k_pnfin(int sel, int n) {
    const float* st = sel ? g_stats1 : g_stats0;
    int l = threadIdx.x;               // 32 threads
    float m = st[l] / (float)n;
    g_pn[l] = m;
    float mm = m * m;
#pragma unroll
    for (int o = 16; o; o >>= 1) mm += __shfl_down_sync(0xffffffffu, mm, o);
    if (l == 0) {
        float var = st[DH] / (float)n - mm;
        g_pn[DH] = rsqrtf(PEPS + var);
    }
}

// ---------------- launch ----------------------------------------------------
extern "C" void kernel_launch(void* const* d_in, const int* in_sizes, int n_in,
                              void* d_out, int out_size) {
    const float* x  = (const float*)d_in[0];
    const int*   ei = (const int*)d_in[1];   // int32 (JAX x64 disabled)
    const float* W0 = (const float*)d_in[2];
    // d_in[3]=b0, d_in[5]=b1 cancel exactly under PairNorm mean subtraction
    const float* W1 = (const float*)d_in[4];
    const float* Wf = (const float*)d_in[6];
    const float* bf = (const float*)d_in[7];
    float*       out = (float*)d_out;

    const int E = in_sizes[1] / 2;
    const int n = in_sizes[0] / DIN;

    const int nbS  = (n + SCAN_B - 1) / SCAN_B;     // scan blocks
    const int AGGB = 148 * 8;                       // grid-stride agg blocks

    // CSR build: A + I with symmetric gcn_norm
    k_zero   <<<(n + 255) / 256, 256>>>(n);
    k_hist   <<<(E + 255) / 256, 256>>>(ei, E);
    k_scan1  <<<nbS, SCAN_B>>>(n);
    k_scan2  <<<1, MAXBLK>>>(nbS);
    k_scan3  <<<nbS, SCAN_B>>>(n, nbS);
    k_scatter<<<(E + n + 255) / 256, 256>>>(ei, E, n);

    // forward
    k_gemm0  <<<(n + 63) / 64, 256>>>(x, W0, n);    // x @ W0 -> A
    k_aggA   <<<AGGB, 256>>>(n);                    // agg(A) -> B, stats0
    k_pnfin  <<<1, 32>>>(0, n);
    k_aggB   <<<AGGB, 256>>>(W1, n);                // agg(pnrelu(B)) @ W1 -> A, stats1
    k_pnfin  <<<1, 32>>>(1, n);
    k_aggC   <<<AGGB, 256>>>(Wf, bf, out, n);       // agg(pnrelu(A)) @ Wf + bf -> out
}